// round 11
// baseline (speedup 1.0000x reference)
#include <cuda_runtime.h>
#include <cuda_fp16.h>

#define N_NODES 50000
#define N_EDGES 800000
#define D_IN    128
#define D_SH    16
#define D_OUT   128
#define N_PATHS 64
#define SCAN_NB ((N_NODES + 255) / 256)              // 196
#define HIST_NB ((N_EDGES + 255) / 256)              // 3125
#define XK_NB   ((N_NODES * 32 + 255) / 256)         // 6250 (half2 pairs)

// ---- static scratch (no allocations allowed) ----
// INVARIANTS at kernel_launch entry (zero-init at load, re-established each run):
//   d_cnt all zero (scan kernel zeroes after read)
//   d_total == 0   (scatter thread 0 resets it)
__device__ int     d_cnt[N_NODES];
__device__ int     d_start[N_NODES];        // segment begin (permuted placement)
__device__ int     d_stop[N_NODES];         // segment end
__device__ int     d_cursor[N_NODES];
__device__ int     d_total;                 // ticket counter for segment placement
__device__ int2    d_edges[N_EDGES];        // CSR payload: {src, e}
__device__ __half2 d_XkH[N_NODES * 32];     // XkH[n,q] = (coeff[2q]*x[n,ki[2q]], coeff[2q+1]*x[n,ki[2q+1]])

// ---- fused histogram + Xk(half2) precompute (independent jobs, one grid) ----
__global__ void __launch_bounds__(256)
hist_xk_kernel(const int* __restrict__ dst,
               const float* __restrict__ x,
               const float* __restrict__ coeff,
               const int* __restrict__ ki) {
    int b = blockIdx.x;
    if (b < HIST_NB) {
        int e = b * 256 + threadIdx.x;
        if (e < N_EDGES) atomicAdd(&d_cnt[dst[e]], 1);
    } else {
        int i = (b - HIST_NB) * 256 + threadIdx.x;
        if (i < N_NODES * 32) {
            int n = i >> 5;
            int q = i & 31;
            int ki0 = __ldg(&ki[2 * q]),     ki1 = __ldg(&ki[2 * q + 1]);
            float c0 = __ldg(&coeff[2 * q]), c1 = __ldg(&coeff[2 * q + 1]);
            float f0 = c0 * __ldg(&x[n * D_IN + ki0]);
            float f1 = c1 * __ldg(&x[n * D_IN + ki1]);
            d_XkH[i] = __floats2half2_rn(f0, f1);
        }
    }
}

// ---- single-pass scan: block-local exclusive scan + atomic ticket offset ----
__global__ void __launch_bounds__(256) scan_kernel() {
    __shared__ int wsum[8];
    __shared__ int blk_off;
    int t = threadIdx.x;
    int lane = t & 31, wid = t >> 5;
    int i = blockIdx.x * 256 + t;

    int v = 0;
    if (i < N_NODES) {
        v = d_cnt[i];
        d_cnt[i] = 0;                        // re-establish invariant
    }
    int s = v;
    #pragma unroll
    for (int off = 1; off < 32; off <<= 1) {
        int u = __shfl_up_sync(0xffffffffu, s, off);
        if (lane >= off) s += u;
    }
    if (lane == 31) wsum[wid] = s;
    __syncthreads();
    if (wid == 0) {
        int ws = (lane < 8) ? wsum[lane] : 0;
        #pragma unroll
        for (int off = 1; off < 8; off <<= 1) {
            int u = __shfl_up_sync(0xffffffffu, ws, off);
            if (lane >= off) ws += u;
        }
        if (lane < 8) wsum[lane] = ws;
    }
    __syncthreads();
    int incl = s + (wid > 0 ? wsum[wid - 1] : 0);
    if (t == 0) blk_off = atomicAdd(&d_total, wsum[7]);
    __syncthreads();

    if (i < N_NODES) {
        int b0 = blk_off + incl - v;
        d_start[i]  = b0;
        d_stop[i]   = b0 + v;
        d_cursor[i] = b0;
    }
}

__global__ void __launch_bounds__(256)
scatter_kernel(const int* __restrict__ src,
               const int* __restrict__ dst) {
    int e = blockIdx.x * blockDim.x + threadIdx.x;
    if (e == 0) d_total = 0;                 // reset ticket for next replay
    if (e < N_EDGES) {
        int d = dst[e];
        int pos = atomicAdd(&d_cursor[d], 1);
        d_edges[pos] = make_int2(src[e], e);
    }
}

// One warp per destination node. Lane l owns paths 2l and 2l+1.
// MIO-op-minimized inner loop: edge descriptors staged in smem and read two-
// at-a-time as uniform LDS.128; sh read by 2 direct per-lane LDGs (both within
// one 64B row -> 1 wavefront each); Xk half2 coalesced.
__global__ void __launch_bounds__(256)
spmm_kernel(const float* __restrict__ sh,
            const int* __restrict__ kj, const int* __restrict__ ko,
            float* __restrict__ out) {
    __shared__ float buf[8][D_OUT];
    __shared__ __align__(16) int2 eds[8][32];
    int l = threadIdx.x & 31;
    int w = threadIdx.x >> 5;
    int node = blockIdx.x * 8 + w;
    if (node >= N_NODES) return;

    int kj0 = __ldg(&kj[2 * l]),  kj1 = __ldg(&kj[2 * l + 1]);
    int ko0 = __ldg(&ko[2 * l]),  ko1 = __ldg(&ko[2 * l + 1]);

    float* bf = buf[w];
    bf[l] = 0.f; bf[l + 32] = 0.f; bf[l + 64] = 0.f; bf[l + 96] = 0.f;

    float acc0 = 0.f, acc1 = 0.f;
    int beg = d_start[node];
    int end = d_stop[node];
    const int4* eds4 = (const int4*)eds[w];

    for (int base = beg; base < end; base += 32) {
        int n = end - base;
        if (n > 32) n = 32;
        if (base + l < end) eds[w][l] = d_edges[base + l];   // coalesced fill
        __syncwarp();

        int j = 0;
        for (; j + 1 < n; j += 2) {
            int4 ee = eds4[j >> 1];        // uniform LDS.128: {srcA,eA,srcB,eB}
            __half2 ha = d_XkH[(size_t)ee.x * 32 + l];
            __half2 hb = d_XkH[(size_t)ee.z * 32 + l];
            const float* ra = sh + (size_t)ee.y * D_SH;
            const float* rb = sh + (size_t)ee.w * D_SH;
            float sa0 = __ldg(ra + kj0);
            float sa1 = __ldg(ra + kj1);
            float sb0 = __ldg(rb + kj0);
            float sb1 = __ldg(rb + kj1);
            float2 xa = __half22float2(ha);
            float2 xb = __half22float2(hb);
            acc0 = fmaf(sa0, xa.x, acc0);
            acc1 = fmaf(sa1, xa.y, acc1);
            acc0 = fmaf(sb0, xb.x, acc0);
            acc1 = fmaf(sb1, xb.y, acc1);
        }
        if (j < n) {
            int2 ea = eds[w][j];           // uniform LDS.64
            __half2 ha = d_XkH[(size_t)ea.x * 32 + l];
            const float* ra = sh + (size_t)ea.y * D_SH;
            float sa0 = __ldg(ra + kj0);
            float sa1 = __ldg(ra + kj1);
            float2 xa = __half22float2(ha);
            acc0 = fmaf(sa0, xa.x, acc0);
            acc1 = fmaf(sa1, xa.y, acc1);
        }
        __syncwarp();
    }

    atomicAdd(bf + ko0, acc0);
    atomicAdd(bf + ko1, acc1);
    __syncwarp();

    size_t o = (size_t)node * D_OUT;
    out[o + l]      = bf[l];
    out[o + l + 32] = bf[l + 32];
    out[o + l + 64] = bf[l + 64];
    out[o + l + 96] = bf[l + 96];
}

extern "C" void kernel_launch(void* const* d_in, const int* in_sizes, int n_in,
                              void* d_out, int out_size) {
    const float* x     = (const float*)d_in[0];
    const float* sh    = (const float*)d_in[1];
    const float* coeff = (const float*)d_in[2];
    const int*   src   = (const int*)d_in[3];
    const int*   dst   = (const int*)d_in[4];
    const int*   ki    = (const int*)d_in[5];
    const int*   kj    = (const int*)d_in[6];
    const int*   ko    = (const int*)d_in[7];
    float* out = (float*)d_out;

    hist_xk_kernel<<<HIST_NB + XK_NB, 256>>>(dst, x, coeff, ki);
    scan_kernel<<<SCAN_NB, 256>>>();
    scatter_kernel<<<HIST_NB, 256>>>(src, dst);
    spmm_kernel<<<(N_NODES + 7) / 8, 256>>>(sh, kj, ko, out);
}

// round 12
// speedup vs baseline: 1.1567x; 1.1567x over previous
#include <cuda_runtime.h>
#include <cuda_fp16.h>

#define N_NODES 50000
#define N_EDGES 800000
#define D_IN    128
#define D_SH    16
#define D_OUT   128
#define N_PATHS 64
#define SCAN_NB ((N_NODES + 255) / 256)              // 196
#define HIST_NB ((N_EDGES + 255) / 256)              // 3125
#define XK_NB   ((N_NODES * 32 + 255) / 256)         // 6250 (half2 pairs)

// ---- static scratch (no allocations allowed) ----
// INVARIANTS at kernel_launch entry (zero-init at load, re-established each run):
//   d_cnt all zero (scan kernel zeroes after read)
//   d_total == 0   (scatter thread 0 resets it)
__device__ int     d_cnt[N_NODES];
__device__ int     d_start[N_NODES];        // segment begin (permuted placement)
__device__ int     d_stop[N_NODES];         // segment end
__device__ int     d_cursor[N_NODES];
__device__ int     d_total;                 // ticket counter for segment placement
__device__ int2    d_edges[N_EDGES];        // CSR payload: {src, e}
__device__ __half2 d_XkH[N_NODES * 32];     // XkH[n,q] = (coeff[2q]*x[n,ki[2q]], coeff[2q+1]*x[n,ki[2q+1]])

// ---- fused histogram + Xk(half2) precompute (independent jobs, one grid) ----
__global__ void __launch_bounds__(256)
hist_xk_kernel(const int* __restrict__ dst,
               const float* __restrict__ x,
               const float* __restrict__ coeff,
               const int* __restrict__ ki) {
    int b = blockIdx.x;
    if (b < HIST_NB) {
        int e = b * 256 + threadIdx.x;
        if (e < N_EDGES) atomicAdd(&d_cnt[dst[e]], 1);
    } else {
        int i = (b - HIST_NB) * 256 + threadIdx.x;
        if (i < N_NODES * 32) {
            int n = i >> 5;
            int q = i & 31;
            int ki0 = __ldg(&ki[2 * q]),     ki1 = __ldg(&ki[2 * q + 1]);
            float c0 = __ldg(&coeff[2 * q]), c1 = __ldg(&coeff[2 * q + 1]);
            float f0 = c0 * __ldg(&x[n * D_IN + ki0]);
            float f1 = c1 * __ldg(&x[n * D_IN + ki1]);
            d_XkH[i] = __floats2half2_rn(f0, f1);
        }
    }
}

// ---- single-pass scan: block-local exclusive scan + atomic ticket offset ----
__global__ void __launch_bounds__(256) scan_kernel() {
    __shared__ int wsum[8];
    __shared__ int blk_off;
    int t = threadIdx.x;
    int lane = t & 31, wid = t >> 5;
    int i = blockIdx.x * 256 + t;

    int v = 0;
    if (i < N_NODES) {
        v = d_cnt[i];
        d_cnt[i] = 0;                        // re-establish invariant
    }
    int s = v;
    #pragma unroll
    for (int off = 1; off < 32; off <<= 1) {
        int u = __shfl_up_sync(0xffffffffu, s, off);
        if (lane >= off) s += u;
    }
    if (lane == 31) wsum[wid] = s;
    __syncthreads();
    if (wid == 0) {
        int ws = (lane < 8) ? wsum[lane] : 0;
        #pragma unroll
        for (int off = 1; off < 8; off <<= 1) {
            int u = __shfl_up_sync(0xffffffffu, ws, off);
            if (lane >= off) ws += u;
        }
        if (lane < 8) wsum[lane] = ws;
    }
    __syncthreads();
    int incl = s + (wid > 0 ? wsum[wid - 1] : 0);
    if (t == 0) blk_off = atomicAdd(&d_total, wsum[7]);
    __syncthreads();

    if (i < N_NODES) {
        int b0 = blk_off + incl - v;
        d_start[i]  = b0;
        d_stop[i]   = b0 + v;
        d_cursor[i] = b0;
    }
}

__global__ void __launch_bounds__(256)
scatter_kernel(const int* __restrict__ src,
               const int* __restrict__ dst) {
    int e = blockIdx.x * blockDim.x + threadIdx.x;
    if (e == 0) d_total = 0;                 // reset ticket for next replay
    if (e < N_EDGES) {
        int d = dst[e];
        int pos = atomicAdd(&d_cursor[d], 1);
        d_edges[pos] = make_int2(src[e], e);
    }
}

// One warp per destination node. Lane l owns paths 2l and 2l+1.
// R10 structure (coalesced edge-desc + shfl broadcast, lane-strided sh LDG +
// shfl), unrolled 4-wide: all 8 desc shfls, then 4 XkH LDGs + 4 sh LDGs issued
// back-to-back before any consumer -> ~8 loads in flight per warp.
__global__ void __launch_bounds__(256)
spmm_kernel(const float* __restrict__ sh,
            const int* __restrict__ kj, const int* __restrict__ ko,
            float* __restrict__ out) {
    __shared__ float buf[8][D_OUT];
    const unsigned FULL = 0xffffffffu;
    int l = threadIdx.x & 31;
    int w = threadIdx.x >> 5;
    int node = blockIdx.x * 8 + w;
    if (node >= N_NODES) return;

    int kj0 = __ldg(&kj[2 * l]),  kj1 = __ldg(&kj[2 * l + 1]);
    int ko0 = __ldg(&ko[2 * l]),  ko1 = __ldg(&ko[2 * l + 1]);

    float* bf = buf[w];
    bf[l] = 0.f; bf[l + 32] = 0.f; bf[l + 64] = 0.f; bf[l + 96] = 0.f;
    __syncwarp();

    float acc0 = 0.f, acc1 = 0.f;
    int beg = d_start[node];
    int end = d_stop[node];
    const int shlane = l & 15;

    for (int base = beg; base < end; base += 32) {
        int n = end - base;
        if (n > 32) n = 32;
        int2 ed = make_int2(0, 0);
        if (base + l < end) ed = d_edges[base + l];   // coalesced

        int j = 0;
        for (; j + 3 < n; j += 4) {
            // broadcast 4 edge descriptors
            int na = __shfl_sync(FULL, ed.x, j);
            int ea = __shfl_sync(FULL, ed.y, j);
            int nb = __shfl_sync(FULL, ed.x, j + 1);
            int eb = __shfl_sync(FULL, ed.y, j + 1);
            int nc = __shfl_sync(FULL, ed.x, j + 2);
            int ec = __shfl_sync(FULL, ed.y, j + 2);
            int nd = __shfl_sync(FULL, ed.x, j + 3);
            int edd = __shfl_sync(FULL, ed.y, j + 3);
            // issue all 8 loads before any use (MLP)
            __half2 ha = d_XkH[(size_t)na * 32 + l];
            __half2 hb = d_XkH[(size_t)nb * 32 + l];
            __half2 hc = d_XkH[(size_t)nc * 32 + l];
            __half2 hd = d_XkH[(size_t)nd * 32 + l];
            float sa = __ldg(sh + (size_t)ea  * D_SH + shlane);
            float sb = __ldg(sh + (size_t)eb  * D_SH + shlane);
            float sc = __ldg(sh + (size_t)ec  * D_SH + shlane);
            float sd = __ldg(sh + (size_t)edd * D_SH + shlane);
            // consume
            float sa0 = __shfl_sync(FULL, sa, kj0);
            float sa1 = __shfl_sync(FULL, sa, kj1);
            float sb0 = __shfl_sync(FULL, sb, kj0);
            float sb1 = __shfl_sync(FULL, sb, kj1);
            float sc0 = __shfl_sync(FULL, sc, kj0);
            float sc1 = __shfl_sync(FULL, sc, kj1);
            float sd0 = __shfl_sync(FULL, sd, kj0);
            float sd1 = __shfl_sync(FULL, sd, kj1);
            float2 xa = __half22float2(ha);
            float2 xb = __half22float2(hb);
            float2 xc = __half22float2(hc);
            float2 xd = __half22float2(hd);
            acc0 = fmaf(sa0, xa.x, acc0);
            acc1 = fmaf(sa1, xa.y, acc1);
            acc0 = fmaf(sb0, xb.x, acc0);
            acc1 = fmaf(sb1, xb.y, acc1);
            acc0 = fmaf(sc0, xc.x, acc0);
            acc1 = fmaf(sc1, xc.y, acc1);
            acc0 = fmaf(sd0, xd.x, acc0);
            acc1 = fmaf(sd1, xd.y, acc1);
        }
        for (; j < n; j++) {
            int na = __shfl_sync(FULL, ed.x, j);
            int ea = __shfl_sync(FULL, ed.y, j);
            __half2 ha = d_XkH[(size_t)na * 32 + l];
            float sa = __ldg(sh + (size_t)ea * D_SH + shlane);
            float sa0 = __shfl_sync(FULL, sa, kj0);
            float sa1 = __shfl_sync(FULL, sa, kj1);
            float2 xa = __half22float2(ha);
            acc0 = fmaf(sa0, xa.x, acc0);
            acc1 = fmaf(sa1, xa.y, acc1);
        }
    }

    atomicAdd(bf + ko0, acc0);
    atomicAdd(bf + ko1, acc1);
    __syncwarp();

    size_t o = (size_t)node * D_OUT;
    out[o + l]      = bf[l];
    out[o + l + 32] = bf[l + 32];
    out[o + l + 64] = bf[l + 64];
    out[o + l + 96] = bf[l + 96];
}

extern "C" void kernel_launch(void* const* d_in, const int* in_sizes, int n_in,
                              void* d_out, int out_size) {
    const float* x     = (const float*)d_in[0];
    const float* sh    = (const float*)d_in[1];
    const float* coeff = (const float*)d_in[2];
    const int*   src   = (const int*)d_in[3];
    const int*   dst   = (const int*)d_in[4];
    const int*   ki    = (const int*)d_in[5];
    const int*   kj    = (const int*)d_in[6];
    const int*   ko    = (const int*)d_in[7];
    float* out = (float*)d_out;

    hist_xk_kernel<<<HIST_NB + XK_NB, 256>>>(dst, x, coeff, ki);
    scan_kernel<<<SCAN_NB, 256>>>();
    scatter_kernel<<<HIST_NB, 256>>>(src, dst);
    spmm_kernel<<<(N_NODES + 7) / 8, 256>>>(sh, kj, ko, out);
}

// round 13
// speedup vs baseline: 1.1608x; 1.0036x over previous
#include <cuda_runtime.h>
#include <cuda_fp16.h>

#define N_NODES 50000
#define N_EDGES 800000
#define D_IN    128
#define D_SH    16
#define D_OUT   128
#define N_PATHS 64
#define SCAN_NB ((N_NODES + 255) / 256)              // 196
#define HIST_NB ((N_EDGES + 255) / 256)              // 3125
#define XK_NB   ((N_NODES * 32 + 255) / 256)         // 6250 (half2 pairs)

// ---- static scratch (no allocations allowed) ----
// INVARIANTS at kernel_launch entry (zero-init at load, re-established each run):
//   d_cnt all zero (scan kernel zeroes after read)
//   d_total == 0   (scatter thread 0 resets it)
__device__ int     d_cnt[N_NODES];
__device__ int     d_start[N_NODES];        // segment begin (permuted placement)
__device__ int     d_stop[N_NODES];         // segment end
__device__ int     d_cursor[N_NODES];
__device__ int     d_total;                 // ticket counter for segment placement
__device__ int2    d_edges[N_EDGES];        // CSR payload: {src, e}
__device__ __half2 d_XkH[N_NODES * 32];     // XkH[n,q] = (coeff[2q]*x[n,ki[2q]], coeff[2q+1]*x[n,ki[2q+1]])

// ---- fused histogram + Xk(half2) precompute (independent jobs, one grid) ----
__global__ void __launch_bounds__(256)
hist_xk_kernel(const int* __restrict__ dst,
               const float* __restrict__ x,
               const float* __restrict__ coeff,
               const int* __restrict__ ki) {
    int b = blockIdx.x;
    if (b < HIST_NB) {
        int e = b * 256 + threadIdx.x;
        if (e < N_EDGES) atomicAdd(&d_cnt[dst[e]], 1);
    } else {
        int i = (b - HIST_NB) * 256 + threadIdx.x;
        if (i < N_NODES * 32) {
            int n = i >> 5;
            int q = i & 31;
            int ki0 = __ldg(&ki[2 * q]),     ki1 = __ldg(&ki[2 * q + 1]);
            float c0 = __ldg(&coeff[2 * q]), c1 = __ldg(&coeff[2 * q + 1]);
            float f0 = c0 * __ldg(&x[n * D_IN + ki0]);
            float f1 = c1 * __ldg(&x[n * D_IN + ki1]);
            d_XkH[i] = __floats2half2_rn(f0, f1);
        }
    }
}

// ---- single-pass scan: block-local exclusive scan + atomic ticket offset ----
__global__ void __launch_bounds__(256) scan_kernel() {
    __shared__ int wsum[8];
    __shared__ int blk_off;
    int t = threadIdx.x;
    int lane = t & 31, wid = t >> 5;
    int i = blockIdx.x * 256 + t;

    int v = 0;
    if (i < N_NODES) {
        v = d_cnt[i];
        d_cnt[i] = 0;                        // re-establish invariant
    }
    int s = v;
    #pragma unroll
    for (int off = 1; off < 32; off <<= 1) {
        int u = __shfl_up_sync(0xffffffffu, s, off);
        if (lane >= off) s += u;
    }
    if (lane == 31) wsum[wid] = s;
    __syncthreads();
    if (wid == 0) {
        int ws = (lane < 8) ? wsum[lane] : 0;
        #pragma unroll
        for (int off = 1; off < 8; off <<= 1) {
            int u = __shfl_up_sync(0xffffffffu, ws, off);
            if (lane >= off) ws += u;
        }
        if (lane < 8) wsum[lane] = ws;
    }
    __syncthreads();
    int incl = s + (wid > 0 ? wsum[wid - 1] : 0);
    if (t == 0) blk_off = atomicAdd(&d_total, wsum[7]);
    __syncthreads();

    if (i < N_NODES) {
        int b0 = blk_off + incl - v;
        d_start[i]  = b0;
        d_stop[i]   = b0 + v;
        d_cursor[i] = b0;
    }
}

__global__ void __launch_bounds__(256)
scatter_kernel(const int* __restrict__ src,
               const int* __restrict__ dst) {
    int e = blockIdx.x * blockDim.x + threadIdx.x;
    if (e == 0) d_total = 0;                 // reset ticket for next replay
    if (e < N_EDGES) {
        int d = dst[e];
        int pos = atomicAdd(&d_cursor[d], 1);
        d_edges[pos] = make_int2(src[e], e);
    }
}

// One warp per destination node. Lane l owns paths 2l and 2l+1.
// MIO-minimized, sync-free inner loop (~4 wavefronts/edge):
//   - edge desc: uniform LDG.64 broadcast (L1-resident window), no shfl
//   - XkH: coalesced 128B half2 load (1 wf)
//   - sh: two direct per-lane LDGs within one 64B row (~1 wf each), no shfl
// 4-wide unroll keeps 4 desc + 12 data loads in flight.
__global__ void __launch_bounds__(256)
spmm_kernel(const float* __restrict__ sh,
            const int* __restrict__ kj, const int* __restrict__ ko,
            float* __restrict__ out) {
    __shared__ float buf[8][D_OUT];
    int l = threadIdx.x & 31;
    int w = threadIdx.x >> 5;
    int node = blockIdx.x * 8 + w;
    if (node >= N_NODES) return;

    int kj0 = __ldg(&kj[2 * l]),  kj1 = __ldg(&kj[2 * l + 1]);
    int ko0 = __ldg(&ko[2 * l]),  ko1 = __ldg(&ko[2 * l + 1]);

    float* bf = buf[w];
    bf[l] = 0.f; bf[l + 32] = 0.f; bf[l + 64] = 0.f; bf[l + 96] = 0.f;
    __syncwarp();

    float acc0 = 0.f, acc1 = 0.f;
    int beg = d_start[node];
    int end = d_stop[node];

    int j = beg;
    for (; j + 3 < end; j += 4) {
        // 4 uniform edge descriptors (broadcast loads, no shuffle)
        int2 e0 = d_edges[j];
        int2 e1 = d_edges[j + 1];
        int2 e2 = d_edges[j + 2];
        int2 e3 = d_edges[j + 3];
        // issue all 12 data loads before any consumer (MLP)
        __half2 h0 = d_XkH[(size_t)e0.x * 32 + l];
        __half2 h1 = d_XkH[(size_t)e1.x * 32 + l];
        __half2 h2 = d_XkH[(size_t)e2.x * 32 + l];
        __half2 h3 = d_XkH[(size_t)e3.x * 32 + l];
        const float* r0 = sh + (size_t)e0.y * D_SH;
        const float* r1 = sh + (size_t)e1.y * D_SH;
        const float* r2 = sh + (size_t)e2.y * D_SH;
        const float* r3 = sh + (size_t)e3.y * D_SH;
        float s00 = __ldg(r0 + kj0), s01 = __ldg(r0 + kj1);
        float s10 = __ldg(r1 + kj0), s11 = __ldg(r1 + kj1);
        float s20 = __ldg(r2 + kj0), s21 = __ldg(r2 + kj1);
        float s30 = __ldg(r3 + kj0), s31 = __ldg(r3 + kj1);
        float2 x0 = __half22float2(h0);
        float2 x1 = __half22float2(h1);
        float2 x2 = __half22float2(h2);
        float2 x3 = __half22float2(h3);
        acc0 = fmaf(s00, x0.x, acc0);
        acc1 = fmaf(s01, x0.y, acc1);
        acc0 = fmaf(s10, x1.x, acc0);
        acc1 = fmaf(s11, x1.y, acc1);
        acc0 = fmaf(s20, x2.x, acc0);
        acc1 = fmaf(s21, x2.y, acc1);
        acc0 = fmaf(s30, x3.x, acc0);
        acc1 = fmaf(s31, x3.y, acc1);
    }
    for (; j < end; j++) {
        int2 e0 = d_edges[j];
        __half2 h0 = d_XkH[(size_t)e0.x * 32 + l];
        const float* r0 = sh + (size_t)e0.y * D_SH;
        float s00 = __ldg(r0 + kj0), s01 = __ldg(r0 + kj1);
        float2 x0 = __half22float2(h0);
        acc0 = fmaf(s00, x0.x, acc0);
        acc1 = fmaf(s01, x0.y, acc1);
    }

    atomicAdd(bf + ko0, acc0);
    atomicAdd(bf + ko1, acc1);
    __syncwarp();

    size_t o = (size_t)node * D_OUT;
    out[o + l]      = bf[l];
    out[o + l + 32] = bf[l + 32];
    out[o + l + 64] = bf[l + 64];
    out[o + l + 96] = bf[l + 96];
}

extern "C" void kernel_launch(void* const* d_in, const int* in_sizes, int n_in,
                              void* d_out, int out_size) {
    const float* x     = (const float*)d_in[0];
    const float* sh    = (const float*)d_in[1];
    const float* coeff = (const float*)d_in[2];
    const int*   src   = (const int*)d_in[3];
    const int*   dst   = (const int*)d_in[4];
    const int*   ki    = (const int*)d_in[5];
    const int*   kj    = (const int*)d_in[6];
    const int*   ko    = (const int*)d_in[7];
    float* out = (float*)d_out;

    hist_xk_kernel<<<HIST_NB + XK_NB, 256>>>(dst, x, coeff, ki);
    scan_kernel<<<SCAN_NB, 256>>>();
    scatter_kernel<<<HIST_NB, 256>>>(src, dst);
    spmm_kernel<<<(N_NODES + 7) / 8, 256>>>(sh, kj, ko, out);
}